// round 14
// baseline (speedup 1.0000x reference)
#include <cuda_runtime.h>
#include <cstdint>

#define NN 200000
#define DD 16
#define KK 16
#define FF 33
#define GN_EPS 1e-5f
#define SLOPE 0.2f

#define NPB 16                      // nodes per chunk (4 warps x 4 nodes)
#define NCHUNK (NN / NPB)           // 12500 exact
#define GRIDB 740                   // persistent blocks (5/SM * 148)
#define NODE_FLOATS 256             // 16 rows x 16 floats, quarter-plane layout
#define BUF_FLOATS (NPB * NODE_FLOATS)

typedef unsigned long long u64;

// Device globals (no allocation allowed)
__device__ float g_buf0[NN * DD];
__device__ float g_buf1[NN * DD];
__device__ int   g_idx32[NN * KK];
__device__ int   g_is64;

__global__ void detect_idx_kernel(const long long* __restrict__ p) {
    int ok = 1;
#pragma unroll 1
    for (int i = 0; i < 32; i++) {
        long long v = p[i];
        if (v < 0 || v >= NN) ok = 0;
    }
    g_is64 = ok;
}

__global__ __launch_bounds__(256) void convert_idx_kernel(const void* __restrict__ idxv) {
    int i = blockIdx.x * 256 + threadIdx.x;
    if (i >= NN * KK) return;
    long long v = g_is64 ? ((const long long*)idxv)[i]
                         : (long long)((const int*)idxv)[i];
    g_idx32[i] = (int)v;
}

__device__ __forceinline__ float leaky(float x) {
    return fmaf(SLOPE, fminf(x, 0.0f), fmaxf(x, 0.0f));
}

__device__ __forceinline__ u64 fma2(u64 a, u64 b, u64 c) {
    u64 d;
    asm("fma.rn.f32x2 %0, %1, %2, %3;" : "=l"(d) : "l"(a), "l"(b), "l"(c));
    return d;
}
__device__ __forceinline__ u64 add2(u64 a, u64 b) {
    u64 d;
    asm("add.rn.f32x2 %0, %1, %2;" : "=l"(d) : "l"(a), "l"(b));
    return d;
}
__device__ __forceinline__ u64 pack2(float lo, float hi) {
    u64 d;
    asm("mov.b64 %0, {%1, %2};" : "=l"(d) : "f"(lo), "f"(hi));
    return d;
}
__device__ __forceinline__ float2 unpack2(u64 v) {
    float2 r;
    asm("mov.b64 {%0, %1}, %2;" : "=f"(r.x), "=f"(r.y) : "l"(v));
    return r;
}

__device__ __forceinline__ void cp_async16(unsigned int smem_dst, const void* gsrc) {
    asm volatile("cp.async.cg.shared.global [%0], [%1], 16;\n" :: "r"(smem_dst), "l"(gsrc));
}
__device__ __forceinline__ void cp_commit() {
    asm volatile("cp.async.commit_group;\n" ::: "memory");
}
__device__ __forceinline__ void cp_wait1() {
    asm volatile("cp.async.wait_group 1;\n" ::: "memory");
}
__device__ __forceinline__ void cp_wait0() {
    asm volatile("cp.async.wait_group 0;\n" ::: "memory");
}

// Persistent kernel, 128 threads = 4 warps; warp w owns nodes {4w..4w+3}.
// g-per-lane with register-resident W1T[g][16:33]; per (node, k) the neighbor
// row is broadcast from staging, each lane runs TWO 4-deep fma2 chains
// (combined with add2) and accumulates hsum[g] locally. base + dk*wdist is
// folded into chain A's init. Epilogue: msg = 16*b2 + hsum @ W2, GN, residual.
__global__ __launch_bounds__(128, 5) void layer_kernel(
    const float* __restrict__ in_feat,   // [NN, DD]
    const float* __restrict__ dists,     // [NN, KK]
    const int*   __restrict__ idx32,     // [NN, KK]
    const float* __restrict__ W1,        // [FF, FF]
    const float* __restrict__ b1,        // [FF]
    const float* __restrict__ W2,        // [FF, DD]
    const float* __restrict__ b2,        // [DD]
    const float* __restrict__ gnw,       // [DD]
    const float* __restrict__ gnb,       // [DD]
    float* __restrict__ out_feat)        // [NN, DD]
{
    __shared__ float snb[2][BUF_FLOATS];   // 2 x 16384 B staging (quarter-plane)
    __shared__ float sW1T[FF][36];         // W1 transposed [g][f]
    __shared__ float sW2T[16][36];         // W2 transposed [d][g]
    __shared__ float sSelf[NPB][33];       // b1[g] + self . W1[0:16][g]
    __shared__ float sHsum[NPB][36];       // per-node sum_k h[k][g]
    __shared__ float sb1v[FF];
    __shared__ float sb2[DD], sgnw[DD], sgnb[DD];

    for (int i = threadIdx.x; i < FF * FF; i += 128) {
        int f = i / FF, g = i % FF;
        sW1T[g][f] = W1[i];
    }
    for (int i = threadIdx.x; i < FF * DD; i += 128) {
        sW2T[i % DD][i / DD] = W2[i];
    }
    if (threadIdx.x < FF) sb1v[threadIdx.x] = b1[threadIdx.x];
    if (threadIdx.x < DD) {
        sb2[threadIdx.x]  = b2[threadIdx.x];
        sgnw[threadIdx.x] = gnw[threadIdx.x];
        sgnb[threadIdx.x] = gnb[threadIdx.x];
    }
    __syncthreads();

    const int tid  = threadIdx.x;
    const int lane = tid & 31;
    const int wrp  = tid >> 5;           // 0..3
    const int half = lane >> 4;          // 0/1
    const int k    = lane & 15;          // edge / channel index
    const int slA  = wrp * 4 + half;     // epilogue node of this half
    const int slB  = slA + 2;

    // Register-resident W1 row for g = lane (16B-aligned: 144*lane + 64)
    const ulonglong2 wA = *reinterpret_cast<const ulonglong2*>(&sW1T[lane][16]);
    const ulonglong2 wB = *reinterpret_cast<const ulonglong2*>(&sW1T[lane][20]);
    const ulonglong2 wC = *reinterpret_cast<const ulonglong2*>(&sW1T[lane][24]);
    const ulonglong2 wD = *reinterpret_cast<const ulonglong2*>(&sW1T[lane][28]);
    const float wdist = sW1T[lane][32];

    // Staging map (warp-local): thread stages rows {2*(tid&7), 2*(tid&7)+1} of node tid>>3.
    const int s_nd = tid >> 3;
    const int s_r0 = (tid & 7) * 2;
    const unsigned int sb0a = (unsigned int)__cvta_generic_to_shared(&snb[0][0]);
    const unsigned int sb1a = (unsigned int)__cvta_generic_to_shared(&snb[1][0]);

    auto stage = [&](int chunk, int par) {
        unsigned int nbase = (par ? sb1a : sb0a) + (unsigned int)(s_nd * 1024);
        int n = chunk * NPB + s_nd;
#pragma unroll
        for (int rr = 0; rr < 2; rr++) {
            int r = s_r0 + rr;
            int jdx = idx32[(size_t)n * KK + r];
            const float* src = in_feat + (size_t)jdx * DD;
            unsigned int dst = nbase + (unsigned int)(r * 16);
            cp_async16(dst,       src);
            cp_async16(dst + 256, src + 4);
            cp_async16(dst + 512, src + 8);
            cp_async16(dst + 768, src + 12);
        }
    };

    int j = blockIdx.x;
    if (j >= NCHUNK) return;
    stage(j, 0);
    cp_commit();
    int par = 0;

#pragma unroll 1
    while (j < NCHUNK) {
        int nxt = j + GRIDB;
        if (nxt < NCHUNK) {
            stage(nxt, par ^ 1);
            cp_commit();
            cp_wait1();
        } else {
            cp_wait0();
        }
        __syncwarp();

        // Prefetch dists of node 0 (broadcast, L2-hot)
        float4 dq0, dq1, dq2, dq3;
        {
            const float4* dp = reinterpret_cast<const float4*>(
                dists + (size_t)(j * NPB + wrp * 4) * KK);
            dq0 = dp[0]; dq1 = dp[1]; dq2 = dp[2]; dq3 = dp[3];
        }

        // ---- sSelf precompute (edge-parallel; lane covers g=k, k+16, [32]) ----
        const int nA = j * NPB + slA;
        const int nB = j * NPB + slB;
#pragma unroll
        for (int pn = 0; pn < 2; pn++) {
            int n = pn ? nB : nA;
            int sl = pn ? slB : slA;
            u64 sf2[8];
            const float4* p = reinterpret_cast<const float4*>(in_feat + (size_t)n * DD);
            float4 a = p[0], b = p[1], c = p[2], d = p[3];
            sf2[0] = pack2(a.x, a.y); sf2[1] = pack2(a.z, a.w);
            sf2[2] = pack2(b.x, b.y); sf2[3] = pack2(b.z, b.w);
            sf2[4] = pack2(c.x, c.y); sf2[5] = pack2(c.z, c.w);
            sf2[6] = pack2(d.x, d.y); sf2[7] = pack2(d.z, d.w);
#pragma unroll
            for (int pass = 0; pass < 2; pass++) {
                int g = k + 16 * pass;
                const u64* w = reinterpret_cast<const u64*>(&sW1T[g][0]);
                u64 accA = fma2(sf2[0], w[0], pack2(sb1v[g], 0.0f));
                accA = fma2(sf2[1], w[1], accA);
                accA = fma2(sf2[2], w[2], accA);
                accA = fma2(sf2[3], w[3], accA);
                u64 accB = fma2(sf2[4], w[4], 0ull);
                accB = fma2(sf2[5], w[5], accB);
                accB = fma2(sf2[6], w[6], accB);
                accB = fma2(sf2[7], w[7], accB);
                float2 uv = unpack2(add2(accA, accB));
                sSelf[sl][g] = uv.x + uv.y;
            }
            if (k == 15) {
                const u64* w = reinterpret_cast<const u64*>(&sW1T[32][0]);
                u64 accA = fma2(sf2[0], w[0], pack2(sb1v[32], 0.0f));
                accA = fma2(sf2[1], w[1], accA);
                accA = fma2(sf2[2], w[2], accA);
                accA = fma2(sf2[3], w[3], accA);
                u64 accB = fma2(sf2[4], w[4], 0ull);
                accB = fma2(sf2[5], w[5], accB);
                accB = fma2(sf2[6], w[6], accB);
                accB = fma2(sf2[7], w[7], accB);
                float2 uv = unpack2(add2(accA, accB));
                sSelf[sl][32] = uv.x + uv.y;
            }
        }
        __syncwarp();

        const float* bufp = &snb[par][0];

        // ---- main: per node, per k: broadcast nb row, two 4-deep chains ----
#pragma unroll
        for (int nd = 0; nd < 4; nd++) {
            const int sl = wrp * 4 + nd;
            float dk[16];
            dk[0]  = dq0.x; dk[1]  = dq0.y; dk[2]  = dq0.z; dk[3]  = dq0.w;
            dk[4]  = dq1.x; dk[5]  = dq1.y; dk[6]  = dq1.z; dk[7]  = dq1.w;
            dk[8]  = dq2.x; dk[9]  = dq2.y; dk[10] = dq2.z; dk[11] = dq2.w;
            dk[12] = dq3.x; dk[13] = dq3.y; dk[14] = dq3.z; dk[15] = dq3.w;
            if (nd < 3) {
                const float4* dp = reinterpret_cast<const float4*>(
                    dists + (size_t)(j * NPB + sl + 1) * KK);
                dq0 = dp[0]; dq1 = dp[1]; dq2 = dp[2]; dq3 = dp[3];
            }
            const float base = sSelf[sl][lane];      // lane-distinct, stride 33: conflict-free
            const float* nb = bufp + sl * NODE_FLOATS;
            float hsum = 0.0f;
#pragma unroll
            for (int kk2 = 0; kk2 < KK; kk2++) {
                ulonglong2 a0 = *reinterpret_cast<const ulonglong2*>(nb + kk2 * 4);
                ulonglong2 a1 = *reinterpret_cast<const ulonglong2*>(nb + 64 + kk2 * 4);
                ulonglong2 a2 = *reinterpret_cast<const ulonglong2*>(nb + 128 + kk2 * 4);
                ulonglong2 a3 = *reinterpret_cast<const ulonglong2*>(nb + 192 + kk2 * 4);
                float basek = fmaf(dk[kk2], wdist, base);
                u64 accA = fma2(a0.x, wA.x, pack2(basek, 0.0f));
                accA = fma2(a0.y, wA.y, accA);
                accA = fma2(a1.x, wB.x, accA);
                accA = fma2(a1.y, wB.y, accA);
                u64 accB = fma2(a2.x, wC.x, 0ull);
                accB = fma2(a2.y, wC.y, accB);
                accB = fma2(a3.x, wD.x, accB);
                accB = fma2(a3.y, wD.y, accB);
                float2 uv = unpack2(add2(accA, accB));
                hsum += leaky(uv.x + uv.y);
            }
            sHsum[sl][lane] = hsum;                  // lane-distinct, stride 36: conflict-free
        }

        // ---- g = 32 side pass (edge-parallel, 2 nodes per pass) ----
        {
            const ulonglong2 v0 = *reinterpret_cast<const ulonglong2*>(&sW1T[32][16]);
            const ulonglong2 v1 = *reinterpret_cast<const ulonglong2*>(&sW1T[32][20]);
            const ulonglong2 v2 = *reinterpret_cast<const ulonglong2*>(&sW1T[32][24]);
            const ulonglong2 v3 = *reinterpret_cast<const ulonglong2*>(&sW1T[32][28]);
            const float wd32 = sW1T[32][32];
#pragma unroll
            for (int p = 0; p < 2; p++) {
                int sl = wrp * 4 + p * 2 + half;
                int n = j * NPB + sl;
                const float* nb = bufp + sl * NODE_FLOATS + k * 4;
                ulonglong2 a0 = *reinterpret_cast<const ulonglong2*>(nb);
                ulonglong2 a1 = *reinterpret_cast<const ulonglong2*>(nb + 64);
                ulonglong2 a2 = *reinterpret_cast<const ulonglong2*>(nb + 128);
                ulonglong2 a3 = *reinterpret_cast<const ulonglong2*>(nb + 192);
                float dkk = dists[(size_t)n * KK + k];
                u64 accA = fma2(a0.x, v0.x, pack2(fmaf(dkk, wd32, sSelf[sl][32]), 0.0f));
                accA = fma2(a0.y, v0.y, accA);
                accA = fma2(a1.x, v1.x, accA);
                accA = fma2(a1.y, v1.y, accA);
                u64 accB = fma2(a2.x, v2.x, 0ull);
                accB = fma2(a2.y, v2.y, accB);
                accB = fma2(a3.x, v3.x, accB);
                accB = fma2(a3.y, v3.y, accB);
                float2 uv = unpack2(add2(accA, accB));
                float h = leaky(uv.x + uv.y);
                h += __shfl_xor_sync(0xffffffffu, h, 1);
                h += __shfl_xor_sync(0xffffffffu, h, 2);
                h += __shfl_xor_sync(0xffffffffu, h, 4);
                h += __shfl_xor_sync(0xffffffffu, h, 8);
                if (k == 0) sHsum[sl][32] = h;
            }
        }
        __syncwarp();

        // ---- epilogue: msg = 16*b2 + hsum @ W2 (lane owns channel d=k) ----
        {
            const float* w2r = &sW2T[k][0];
            const float* hsA = &sHsum[slA][0];
            const float* hsB = &sHsum[slB][0];
            float mA0 = 16.0f * sb2[k], mA1 = 0.0f;
            float mB0 = mA0, mB1 = 0.0f;
#pragma unroll
            for (int jj = 0; jj < 4; jj++) {
                float4 w  = *reinterpret_cast<const float4*>(w2r + 8 * jj);
                float4 ha = *reinterpret_cast<const float4*>(hsA + 8 * jj);
                float4 hb = *reinterpret_cast<const float4*>(hsB + 8 * jj);
                mA0 += ha.x * w.x + ha.y * w.y + ha.z * w.z + ha.w * w.w;
                mB0 += hb.x * w.x + hb.y * w.y + hb.z * w.z + hb.w * w.w;
                float4 w2  = *reinterpret_cast<const float4*>(w2r + 8 * jj + 4);
                float4 ha2 = *reinterpret_cast<const float4*>(hsA + 8 * jj + 4);
                float4 hb2 = *reinterpret_cast<const float4*>(hsB + 8 * jj + 4);
                mA1 += ha2.x * w2.x + ha2.y * w2.y + ha2.z * w2.z + ha2.w * w2.w;
                mB1 += hb2.x * w2.x + hb2.y * w2.y + hb2.z * w2.z + hb2.w * w2.w;
            }
            float mA = fmaf(hsA[32], w2r[32], mA0 + mA1);
            float mB = fmaf(hsB[32], w2r[32], mB0 + mB1);

            // GroupNorm stats over the 8-lane channel group (d 0-7 | 8-15)
            float muA = mA, m2A = mA * mA;
            float muB = mB, m2B = mB * mB;
#pragma unroll
            for (int off = 1; off < 8; off <<= 1) {
                muA += __shfl_xor_sync(0xffffffffu, muA, off);
                m2A += __shfl_xor_sync(0xffffffffu, m2A, off);
                muB += __shfl_xor_sync(0xffffffffu, muB, off);
                m2B += __shfl_xor_sync(0xffffffffu, m2B, off);
            }
            muA *= 0.125f; muB *= 0.125f;
            float invA = rsqrtf(fmaf(-muA, muA, m2A * 0.125f) + GN_EPS);
            float invB = rsqrtf(fmaf(-muB, muB, m2B * 0.125f) + GN_EPS);
            float oA = in_feat[(size_t)nA * DD + k] +
                       leaky(fmaf((mA - muA) * invA, sgnw[k], sgnb[k]));
            float oB = in_feat[(size_t)nB * DD + k] +
                       leaky(fmaf((mB - muB) * invB, sgnw[k], sgnb[k]));
            out_feat[(size_t)nA * DD + k] = oA;
            out_feat[(size_t)nB * DD + k] = oB;
        }

        par ^= 1;
        j = nxt;
    }
}

extern "C" void kernel_launch(void* const* d_in, const int* in_sizes, int n_in,
                              void* d_out, int out_size) {
    const float* y     = (const float*)d_in[0];
    const float* dists = (const float*)d_in[1];
    const float* W1    = (const float*)d_in[2];
    const float* b1    = (const float*)d_in[3];
    const float* W2    = (const float*)d_in[4];
    const float* b2    = (const float*)d_in[5];
    const float* gnw   = (const float*)d_in[6];
    const float* gnb   = (const float*)d_in[7];
    const void*  idx   = (const void*)d_in[8];
    float* out = (float*)d_out;

    float *buf0, *buf1;
    int* idx32;
    cudaGetSymbolAddress((void**)&buf0, g_buf0);
    cudaGetSymbolAddress((void**)&buf1, g_buf1);
    cudaGetSymbolAddress((void**)&idx32, g_idx32);

    detect_idx_kernel<<<1, 1>>>((const long long*)idx);
    convert_idx_kernel<<<(NN * KK + 255) / 256, 256>>>(idx);

    layer_kernel<<<GRIDB, 128>>>(y,    dists, idx32, W1,               b1,          W2,               b2,          gnw,          gnb,          buf0);
    layer_kernel<<<GRIDB, 128>>>(buf0, dists, idx32, W1 + 1 * FF * FF, b1 + 1 * FF, W2 + 1 * FF * DD, b2 + 1 * DD, gnw + 1 * DD, gnb + 1 * DD, buf1);
    layer_kernel<<<GRIDB, 128>>>(buf1, dists, idx32, W1 + 2 * FF * FF, b1 + 2 * FF, W2 + 2 * FF * DD, b2 + 2 * DD, gnw + 2 * DD, gnb + 2 * DD, out);
}

// round 15
// speedup vs baseline: 1.0006x; 1.0006x over previous
#include <cuda_runtime.h>
#include <cstdint>

#define NN 200000
#define DD 16
#define KK 16
#define FF 33
#define GN_EPS 1e-5f
#define SLOPE 0.2f

#define NPB 16                      // nodes per chunk (4 warps x 4 nodes)
#define NCHUNK (NN / NPB)           // 12500 exact
#define GRIDB 740                   // persistent blocks (5/SM * 148)
#define NODE_FLOATS 256             // 16 rows x 16 floats, quarter-plane layout
#define BUF_FLOATS (NPB * NODE_FLOATS)

typedef unsigned long long u64;

// Device globals (no allocation allowed)
__device__ float g_buf0[NN * DD];
__device__ float g_buf1[NN * DD];
__device__ int   g_idx32[NN * KK];
__device__ int   g_is64;

__global__ void detect_idx_kernel(const long long* __restrict__ p) {
    int ok = 1;
#pragma unroll 1
    for (int i = 0; i < 32; i++) {
        long long v = p[i];
        if (v < 0 || v >= NN) ok = 0;
    }
    g_is64 = ok;
}

__global__ __launch_bounds__(256) void convert_idx_kernel(const void* __restrict__ idxv) {
    int i = blockIdx.x * 256 + threadIdx.x;
    if (i >= NN * KK) return;
    long long v = g_is64 ? ((const long long*)idxv)[i]
                         : (long long)((const int*)idxv)[i];
    g_idx32[i] = (int)v;
}

__device__ __forceinline__ float leaky(float x) {
    return fmaf(SLOPE, fminf(x, 0.0f), fmaxf(x, 0.0f));
}

__device__ __forceinline__ u64 fma2(u64 a, u64 b, u64 c) {
    u64 d;
    asm("fma.rn.f32x2 %0, %1, %2, %3;" : "=l"(d) : "l"(a), "l"(b), "l"(c));
    return d;
}
__device__ __forceinline__ u64 add2(u64 a, u64 b) {
    u64 d;
    asm("add.rn.f32x2 %0, %1, %2;" : "=l"(d) : "l"(a), "l"(b));
    return d;
}
__device__ __forceinline__ u64 pack2(float lo, float hi) {
    u64 d;
    asm("mov.b64 %0, {%1, %2};" : "=l"(d) : "f"(lo), "f"(hi));
    return d;
}
__device__ __forceinline__ float2 unpack2(u64 v) {
    float2 r;
    asm("mov.b64 {%0, %1}, %2;" : "=f"(r.x), "=f"(r.y) : "l"(v));
    return r;
}

__device__ __forceinline__ void cp_async16(unsigned int smem_dst, const void* gsrc) {
    asm volatile("cp.async.cg.shared.global [%0], [%1], 16;\n" :: "r"(smem_dst), "l"(gsrc));
}
__device__ __forceinline__ void cp_commit() {
    asm volatile("cp.async.commit_group;\n" ::: "memory");
}
__device__ __forceinline__ void cp_wait1() {
    asm volatile("cp.async.wait_group 1;\n" ::: "memory");
}
__device__ __forceinline__ void cp_wait0() {
    asm volatile("cp.async.wait_group 0;\n" ::: "memory");
}

// Persistent kernel, 128 threads = 4 warps; warp w owns nodes {4w..4w+3}.
// g-per-lane with register-resident W1T[g][16:33]; per (node, k) the neighbor
// row is broadcast from staging, lanes accumulate hsum[g] locally.
// GATHER COALESCING: staging maps 4 consecutive lanes to the 4 quarters of ONE
// row -> each warp cp.async instruction covers 8 rows with the 4 lanes of a
// group hitting the same 64B-aligned line (1 line-access/row, was 4).
__global__ __launch_bounds__(128, 5) void layer_kernel(
    const float* __restrict__ in_feat,   // [NN, DD]
    const float* __restrict__ dists,     // [NN, KK]
    const int*   __restrict__ idx32,     // [NN, KK]
    const float* __restrict__ W1,        // [FF, FF]
    const float* __restrict__ b1,        // [FF]
    const float* __restrict__ W2,        // [FF, DD]
    const float* __restrict__ b2,        // [DD]
    const float* __restrict__ gnw,       // [DD]
    const float* __restrict__ gnb,       // [DD]
    float* __restrict__ out_feat)        // [NN, DD]
{
    __shared__ float snb[2][BUF_FLOATS];   // 2 x 16384 B staging (quarter-plane)
    __shared__ float sW1T[FF][36];         // W1 transposed [g][f]
    __shared__ float sW2T[16][36];         // W2 transposed [d][g]
    __shared__ float sSelf[NPB][33];       // b1[g] + self . W1[0:16][g]
    __shared__ float sHsum[NPB][36];       // per-node sum_k h[k][g]
    __shared__ float sb1v[FF];
    __shared__ float sb2[DD], sgnw[DD], sgnb[DD];

    for (int i = threadIdx.x; i < FF * FF; i += 128) {
        int f = i / FF, g = i % FF;
        sW1T[g][f] = W1[i];
    }
    for (int i = threadIdx.x; i < FF * DD; i += 128) {
        sW2T[i % DD][i / DD] = W2[i];
    }
    if (threadIdx.x < FF) sb1v[threadIdx.x] = b1[threadIdx.x];
    if (threadIdx.x < DD) {
        sb2[threadIdx.x]  = b2[threadIdx.x];
        sgnw[threadIdx.x] = gnw[threadIdx.x];
        sgnb[threadIdx.x] = gnb[threadIdx.x];
    }
    __syncthreads();

    const int tid  = threadIdx.x;
    const int lane = tid & 31;
    const int wrp  = tid >> 5;           // 0..3
    const int half = lane >> 4;          // 0/1
    const int k    = lane & 15;          // edge / channel index
    const int slA  = wrp * 4 + half;     // epilogue node of this half
    const int slB  = slA + 2;

    // Register-resident W1 row for g = lane (16B-aligned: 144*lane + 64)
    const ulonglong2 wA = *reinterpret_cast<const ulonglong2*>(&sW1T[lane][16]);
    const ulonglong2 wB = *reinterpret_cast<const ulonglong2*>(&sW1T[lane][20]);
    const ulonglong2 wC = *reinterpret_cast<const ulonglong2*>(&sW1T[lane][24]);
    const ulonglong2 wD = *reinterpret_cast<const ulonglong2*>(&sW1T[lane][28]);
    const float wdist = sW1T[lane][32];

    const unsigned int sb0a = (unsigned int)__cvta_generic_to_shared(&snb[0][0]);
    const unsigned int sb1a = (unsigned int)__cvta_generic_to_shared(&snb[1][0]);

    // Coalesced staging (warp-local): lane = 4*ri + q. Instruction i covers the
    // 8 rows {i*8+ri}; the 4 lanes of a group fetch quarters q of ONE row
    // (same 64B line -> 1 line access). Dest: node*1024 + q*256 + k*16 bytes.
    const int s_ri = lane >> 2;          // row group 0..7
    const int s_q  = lane & 3;           // quarter 0..3
    auto stage = [&](int chunk, int par) {
        unsigned int nbase = (par ? sb1a : sb0a) + (unsigned int)(wrp * 4096);
        const int* irow = idx32 + (size_t)(chunk * NPB + wrp * 4) * KK;
#pragma unroll
        for (int i = 0; i < 8; i++) {
            int row = i * 8 + s_ri;       // 0..63 within this warp's 4 nodes
            int jdx = irow[row];          // 4-lane broadcast LDG, L1-hot
            cp_async16(nbase + (unsigned int)(((row >> 4) << 10) + (s_q << 8) + ((row & 15) << 4)),
                       in_feat + (size_t)jdx * DD + (s_q << 2));
        }
    };

    int j = blockIdx.x;
    if (j >= NCHUNK) return;
    stage(j, 0);
    cp_commit();
    int par = 0;

#pragma unroll 1
    while (j < NCHUNK) {
        int nxt = j + GRIDB;
        if (nxt < NCHUNK) {
            stage(nxt, par ^ 1);
            cp_commit();
            cp_wait1();
        } else {
            cp_wait0();
        }
        __syncwarp();

        // Prefetch dists of node 0 (broadcast, L2-hot)
        float4 dq0, dq1, dq2, dq3;
        {
            const float4* dp = reinterpret_cast<const float4*>(
                dists + (size_t)(j * NPB + wrp * 4) * KK);
            dq0 = dp[0]; dq1 = dp[1]; dq2 = dp[2]; dq3 = dp[3];
        }

        // ---- sSelf precompute (edge-parallel; lane covers g=k, k+16, [32]) ----
        const int nA = j * NPB + slA;
        const int nB = j * NPB + slB;
#pragma unroll
        for (int pn = 0; pn < 2; pn++) {
            int n = pn ? nB : nA;
            int sl = pn ? slB : slA;
            u64 sf2[8];
            const float4* p = reinterpret_cast<const float4*>(in_feat + (size_t)n * DD);
            float4 a = p[0], b = p[1], c = p[2], d = p[3];
            sf2[0] = pack2(a.x, a.y); sf2[1] = pack2(a.z, a.w);
            sf2[2] = pack2(b.x, b.y); sf2[3] = pack2(b.z, b.w);
            sf2[4] = pack2(c.x, c.y); sf2[5] = pack2(c.z, c.w);
            sf2[6] = pack2(d.x, d.y); sf2[7] = pack2(d.z, d.w);
#pragma unroll
            for (int pass = 0; pass < 2; pass++) {
                int g = k + 16 * pass;
                const u64* w = reinterpret_cast<const u64*>(&sW1T[g][0]);
                u64 accA = fma2(sf2[0], w[0], pack2(sb1v[g], 0.0f));
                accA = fma2(sf2[1], w[1], accA);
                accA = fma2(sf2[2], w[2], accA);
                accA = fma2(sf2[3], w[3], accA);
                u64 accB = fma2(sf2[4], w[4], 0ull);
                accB = fma2(sf2[5], w[5], accB);
                accB = fma2(sf2[6], w[6], accB);
                accB = fma2(sf2[7], w[7], accB);
                float2 uv = unpack2(add2(accA, accB));
                sSelf[sl][g] = uv.x + uv.y;
            }
            if (k == 15) {
                const u64* w = reinterpret_cast<const u64*>(&sW1T[32][0]);
                u64 accA = fma2(sf2[0], w[0], pack2(sb1v[32], 0.0f));
                accA = fma2(sf2[1], w[1], accA);
                accA = fma2(sf2[2], w[2], accA);
                accA = fma2(sf2[3], w[3], accA);
                u64 accB = fma2(sf2[4], w[4], 0ull);
                accB = fma2(sf2[5], w[5], accB);
                accB = fma2(sf2[6], w[6], accB);
                accB = fma2(sf2[7], w[7], accB);
                float2 uv = unpack2(add2(accA, accB));
                sSelf[sl][32] = uv.x + uv.y;
            }
        }
        __syncwarp();

        const float* bufp = &snb[par][0];

        // ---- main: per node, per k: broadcast nb row, two 4-deep chains ----
#pragma unroll
        for (int nd = 0; nd < 4; nd++) {
            const int sl = wrp * 4 + nd;
            float dk[16];
            dk[0]  = dq0.x; dk[1]  = dq0.y; dk[2]  = dq0.z; dk[3]  = dq0.w;
            dk[4]  = dq1.x; dk[5]  = dq1.y; dk[6]  = dq1.z; dk[7]  = dq1.w;
            dk[8]  = dq2.x; dk[9]  = dq2.y; dk[10] = dq2.z; dk[11] = dq2.w;
            dk[12] = dq3.x; dk[13] = dq3.y; dk[14] = dq3.z; dk[15] = dq3.w;
            if (nd < 3) {
                const float4* dp = reinterpret_cast<const float4*>(
                    dists + (size_t)(j * NPB + sl + 1) * KK);
                dq0 = dp[0]; dq1 = dp[1]; dq2 = dp[2]; dq3 = dp[3];
            }
            const float base = sSelf[sl][lane];      // lane-distinct, stride 33: conflict-free
            const float* nb = bufp + sl * NODE_FLOATS;
            float hsum = 0.0f;
#pragma unroll
            for (int kk2 = 0; kk2 < KK; kk2++) {
                ulonglong2 a0 = *reinterpret_cast<const ulonglong2*>(nb + kk2 * 4);
                ulonglong2 a1 = *reinterpret_cast<const ulonglong2*>(nb + 64 + kk2 * 4);
                ulonglong2 a2 = *reinterpret_cast<const ulonglong2*>(nb + 128 + kk2 * 4);
                ulonglong2 a3 = *reinterpret_cast<const ulonglong2*>(nb + 192 + kk2 * 4);
                float basek = fmaf(dk[kk2], wdist, base);
                u64 accA = fma2(a0.x, wA.x, pack2(basek, 0.0f));
                accA = fma2(a0.y, wA.y, accA);
                accA = fma2(a1.x, wB.x, accA);
                accA = fma2(a1.y, wB.y, accA);
                u64 accB = fma2(a2.x, wC.x, 0ull);
                accB = fma2(a2.y, wC.y, accB);
                accB = fma2(a3.x, wD.x, accB);
                accB = fma2(a3.y, wD.y, accB);
                float2 uv = unpack2(add2(accA, accB));
                hsum += leaky(uv.x + uv.y);
            }
            sHsum[sl][lane] = hsum;                  // lane-distinct, stride 36: conflict-free
        }

        // ---- g = 32 side pass (edge-parallel, 2 nodes per pass) ----
        {
            const ulonglong2 v0 = *reinterpret_cast<const ulonglong2*>(&sW1T[32][16]);
            const ulonglong2 v1 = *reinterpret_cast<const ulonglong2*>(&sW1T[32][20]);
            const ulonglong2 v2 = *reinterpret_cast<const ulonglong2*>(&sW1T[32][24]);
            const ulonglong2 v3 = *reinterpret_cast<const ulonglong2*>(&sW1T[32][28]);
            const float wd32 = sW1T[32][32];
#pragma unroll
            for (int p = 0; p < 2; p++) {
                int sl = wrp * 4 + p * 2 + half;
                int n = j * NPB + sl;
                const float* nb = bufp + sl * NODE_FLOATS + k * 4;
                ulonglong2 a0 = *reinterpret_cast<const ulonglong2*>(nb);
                ulonglong2 a1 = *reinterpret_cast<const ulonglong2*>(nb + 64);
                ulonglong2 a2 = *reinterpret_cast<const ulonglong2*>(nb + 128);
                ulonglong2 a3 = *reinterpret_cast<const ulonglong2*>(nb + 192);
                float dkk = dists[(size_t)n * KK + k];
                u64 accA = fma2(a0.x, v0.x, pack2(fmaf(dkk, wd32, sSelf[sl][32]), 0.0f));
                accA = fma2(a0.y, v0.y, accA);
                accA = fma2(a1.x, v1.x, accA);
                accA = fma2(a1.y, v1.y, accA);
                u64 accB = fma2(a2.x, v2.x, 0ull);
                accB = fma2(a2.y, v2.y, accB);
                accB = fma2(a3.x, v3.x, accB);
                accB = fma2(a3.y, v3.y, accB);
                float2 uv = unpack2(add2(accA, accB));
                float h = leaky(uv.x + uv.y);
                h += __shfl_xor_sync(0xffffffffu, h, 1);
                h += __shfl_xor_sync(0xffffffffu, h, 2);
                h += __shfl_xor_sync(0xffffffffu, h, 4);
                h += __shfl_xor_sync(0xffffffffu, h, 8);
                if (k == 0) sHsum[sl][32] = h;
            }
        }
        __syncwarp();

        // ---- epilogue: msg = 16*b2 + hsum @ W2 (lane owns channel d=k) ----
        {
            const float* w2r = &sW2T[k][0];
            const float* hsA = &sHsum[slA][0];
            const float* hsB = &sHsum[slB][0];
            float mA0 = 16.0f * sb2[k], mA1 = 0.0f;
            float mB0 = mA0, mB1 = 0.0f;
#pragma unroll
            for (int jj = 0; jj < 4; jj++) {
                float4 w  = *reinterpret_cast<const float4*>(w2r + 8 * jj);
                float4 ha = *reinterpret_cast<const float4*>(hsA + 8 * jj);
                float4 hb = *reinterpret_cast<const float4*>(hsB + 8 * jj);
                mA0 += ha.x * w.x + ha.y * w.y + ha.z * w.z + ha.w * w.w;
                mB0 += hb.x * w.x + hb.y * w.y + hb.z * w.z + hb.w * w.w;
                float4 w2  = *reinterpret_cast<const float4*>(w2r + 8 * jj + 4);
                float4 ha2 = *reinterpret_cast<const float4*>(hsA + 8 * jj + 4);
                float4 hb2 = *reinterpret_cast<const float4*>(hsB + 8 * jj + 4);
                mA1 += ha2.x * w2.x + ha2.y * w2.y + ha2.z * w2.z + ha2.w * w2.w;
                mB1 += hb2.x * w2.x + hb2.y * w2.y + hb2.z * w2.z + hb2.w * w2.w;
            }
            float mA = fmaf(hsA[32], w2r[32], mA0 + mA1);
            float mB = fmaf(hsB[32], w2r[32], mB0 + mB1);

            // GroupNorm stats over the 8-lane channel group (d 0-7 | 8-15)
            float muA = mA, m2A = mA * mA;
            float muB = mB, m2B = mB * mB;
#pragma unroll
            for (int off = 1; off < 8; off <<= 1) {
                muA += __shfl_xor_sync(0xffffffffu, muA, off);
                m2A += __shfl_xor_sync(0xffffffffu, m2A, off);
                muB += __shfl_xor_sync(0xffffffffu, muB, off);
                m2B += __shfl_xor_sync(0xffffffffu, m2B, off);
            }
            muA *= 0.125f; muB *= 0.125f;
            float invA = rsqrtf(fmaf(-muA, muA, m2A * 0.125f) + GN_EPS);
            float invB = rsqrtf(fmaf(-muB, muB, m2B * 0.125f) + GN_EPS);
            float oA = in_feat[(size_t)nA * DD + k] +
                       leaky(fmaf((mA - muA) * invA, sgnw[k], sgnb[k]));
            float oB = in_feat[(size_t)nB * DD + k] +
                       leaky(fmaf((mB - muB) * invB, sgnw[k], sgnb[k]));
            out_feat[(size_t)nA * DD + k] = oA;
            out_feat[(size_t)nB * DD + k] = oB;
        }

        par ^= 1;
        j = nxt;
    }
}

extern "C" void kernel_launch(void* const* d_in, const int* in_sizes, int n_in,
                              void* d_out, int out_size) {
    const float* y     = (const float*)d_in[0];
    const float* dists = (const float*)d_in[1];
    const float* W1    = (const float*)d_in[2];
    const float* b1    = (const float*)d_in[3];
    const float* W2    = (const float*)d_in[4];
    const float* b2    = (const float*)d_in[5];
    const float* gnw   = (const float*)d_in[6];
    const float* gnb   = (const float*)d_in[7];
    const void*  idx   = (const void*)d_in[8];
    float* out = (float*)d_out;

    float *buf0, *buf1;
    int* idx32;
    cudaGetSymbolAddress((void**)&buf0, g_buf0);
    cudaGetSymbolAddress((void**)&buf1, g_buf1);
    cudaGetSymbolAddress((void**)&idx32, g_idx32);

    detect_idx_kernel<<<1, 1>>>((const long long*)idx);
    convert_idx_kernel<<<(NN * KK + 255) / 256, 256>>>(idx);

    layer_kernel<<<GRIDB, 128>>>(y,    dists, idx32, W1,               b1,          W2,               b2,          gnw,          gnb,          buf0);
    layer_kernel<<<GRIDB, 128>>>(buf0, dists, idx32, W1 + 1 * FF * FF, b1 + 1 * FF, W2 + 1 * FF * DD, b2 + 1 * DD, gnw + 1 * DD, gnb + 1 * DD, buf1);
    layer_kernel<<<GRIDB, 128>>>(buf1, dists, idx32, W1 + 2 * FF * FF, b1 + 2 * FF, W2 + 2 * FF * DD, b2 + 2 * DD, gnw + 2 * DD, gnb + 2 * DD, out);
}